// round 4
// baseline (speedup 1.0000x reference)
#include <cuda_runtime.h>

#define N_NODES 100000
#define D 128

// Scratch (device globals: no allocations allowed in kernel_launch)
__device__ float g_agg[N_NODES * D];   // 51.2 MB aggregation buffer
__device__ float g_h1 [N_NODES * D];   // layer-1 activations
__device__ float g_h2 [N_NODES * D];   // layer-2 activations
__device__ float g_deg[N_NODES];       // degree -> inv degree (in place)

// ---------------------------------------------------------------------------
// Zero a buffer (float4 granularity; n4 = element count / 4)
// ---------------------------------------------------------------------------
__global__ void k_zero(float* __restrict__ p, int n4) {
    int i = blockIdx.x * blockDim.x + threadIdx.x;
    if (i < n4) ((float4*)p)[i] = make_float4(0.f, 0.f, 0.f, 0.f);
}

// ---------------------------------------------------------------------------
// Edge scatter: one warp per edge. Gather 512B row of src, vector-reduce into
// agg[dst]. Optionally count degree (layer 1 only).
// ---------------------------------------------------------------------------
__global__ void k_scatter(const float* __restrict__ x,
                          const int*   __restrict__ src,
                          const int*   __restrict__ dst,
                          float* __restrict__ agg,
                          float* __restrict__ deg,   // nullptr on layer 2
                          int E) {
    int gid  = blockIdx.x * blockDim.x + threadIdx.x;
    int e    = gid >> 5;
    int lane = gid & 31;
    if (e >= E) return;
    int s = __ldg(src + e);
    int d = __ldg(dst + e);
    float4 v = ((const float4*)(x + (size_t)s * D))[lane];
    float* a = agg + (size_t)d * D + lane * 4;
    asm volatile("red.global.add.v4.f32 [%0], {%1,%2,%3,%4};"
                 :: "l"(a), "f"(v.x), "f"(v.y), "f"(v.z), "f"(v.w)
                 : "memory");
    if (deg != nullptr && lane == 0) atomicAdd(deg + d, 1.0f);
}

// ---------------------------------------------------------------------------
// deg[i] -> 1 / max(deg[i], 1)
// ---------------------------------------------------------------------------
__global__ void k_invdeg(float* __restrict__ deg, int n) {
    int i = blockIdx.x * blockDim.x + threadIdx.x;
    if (i < n) deg[i] = 1.0f / fmaxf(deg[i], 1.0f);
}

// ---------------------------------------------------------------------------
// Fused SAGE layer GEMM:
//   out[m, :] = act( (agg[m,:] * inv[m]) @ Wl^T + bias + A2[m,:] @ Wr^T )
// Treated as M x 256 x 128 GEMM in two K-phases.
// Block: 256 threads, tile 64 rows x 128 cols; thread microtile 8x4.
// ---------------------------------------------------------------------------
template<bool RELU>
__global__ void __launch_bounds__(256)
k_sage_gemm(const float* __restrict__ A1,    // agg
            const float* __restrict__ inv,   // inverse degree
            const float* __restrict__ A2,    // x or h1
            const float* __restrict__ Wl,
            const float* __restrict__ bias,
            const float* __restrict__ Wr,
            float* __restrict__ out, int M) {
    __shared__ float As[16][68];    // [k][row], padded (stride 272B, 16B-aligned)
    __shared__ float Bs[16][132];   // [k][col], padded (stride 528B, 16B-aligned)

    const int t    = threadIdx.x;
    const int lane = t & 31;   // column group: cols [4*lane, 4*lane+3]
    const int wrp  = t >> 5;   // row group:    rows [8*wrp, 8*wrp+7]
    const int m0   = blockIdx.x * 64;

    float acc[8][4];
    #pragma unroll
    for (int i = 0; i < 8; ++i)
        #pragma unroll
        for (int j = 0; j < 4; ++j) acc[i][j] = 0.f;

    #pragma unroll
    for (int p = 0; p < 2; ++p) {
        const float* A = p ? A2 : A1;
        const float* W = p ? Wr : Wl;
        for (int kc = 0; kc < D; kc += 16) {
            // --- stage A tile: 64 rows x 16 k (transposed to [k][row]) ---
            {
                int r   = t >> 2;           // 0..63
                int k4  = (t & 3) * 4;      // 0,4,8,12
                int row = m0 + r;
                float4 v = make_float4(0.f, 0.f, 0.f, 0.f);
                if (row < M) {
                    v = *(const float4*)(A + (size_t)row * D + kc + k4);
                    if (p == 0) {
                        float sc = inv[row];
                        v.x *= sc; v.y *= sc; v.z *= sc; v.w *= sc;
                    }
                }
                As[k4 + 0][r] = v.x;
                As[k4 + 1][r] = v.y;
                As[k4 + 2][r] = v.z;
                As[k4 + 3][r] = v.w;
            }
            // --- stage B tile: Bs[k][n] = W[n][kc+k], 16 x 128 ---
            {
                int n  = t >> 1;            // 0..127
                int k8 = (t & 1) * 8;       // 0 or 8
                const float4* wp = (const float4*)(W + (size_t)n * D + kc + k8);
                float4 u0 = wp[0], u1 = wp[1];
                Bs[k8 + 0][n] = u0.x; Bs[k8 + 1][n] = u0.y;
                Bs[k8 + 2][n] = u0.z; Bs[k8 + 3][n] = u0.w;
                Bs[k8 + 4][n] = u1.x; Bs[k8 + 5][n] = u1.y;
                Bs[k8 + 6][n] = u1.z; Bs[k8 + 7][n] = u1.w;
            }
            __syncthreads();
            #pragma unroll
            for (int k = 0; k < 16; ++k) {
                const float4 b4 = *(const float4*)&Bs[k][lane * 4];
                const float4 a0 = *(const float4*)&As[k][wrp * 8];     // warp-broadcast
                const float4 a1 = *(const float4*)&As[k][wrp * 8 + 4]; // warp-broadcast
                float av[8] = {a0.x, a0.y, a0.z, a0.w, a1.x, a1.y, a1.z, a1.w};
                #pragma unroll
                for (int i = 0; i < 8; ++i) {
                    acc[i][0] = fmaf(av[i], b4.x, acc[i][0]);
                    acc[i][1] = fmaf(av[i], b4.y, acc[i][1]);
                    acc[i][2] = fmaf(av[i], b4.z, acc[i][2]);
                    acc[i][3] = fmaf(av[i], b4.w, acc[i][3]);
                }
            }
            __syncthreads();
        }
    }

    // --- epilogue: bias + relu + store ---
    const float4 bb = *(const float4*)(bias + lane * 4);
    #pragma unroll
    for (int i = 0; i < 8; ++i) {
        int row = m0 + wrp * 8 + i;
        if (row < M) {
            float4 o;
            o.x = acc[i][0] + bb.x;
            o.y = acc[i][1] + bb.y;
            o.z = acc[i][2] + bb.z;
            o.w = acc[i][3] + bb.w;
            if (RELU) {
                o.x = fmaxf(o.x, 0.f); o.y = fmaxf(o.y, 0.f);
                o.z = fmaxf(o.z, 0.f); o.w = fmaxf(o.w, 0.f);
            }
            *(float4*)(out + (size_t)row * D + lane * 4) = o;
        }
    }
}

// ---------------------------------------------------------------------------
// Output layer: out[m, 0..3] = h[m,:] @ w_out^T + b_out.  One warp per row.
// ---------------------------------------------------------------------------
__global__ void k_out(const float* __restrict__ h,
                      const float* __restrict__ w,
                      const float* __restrict__ b,
                      float* __restrict__ out, int M) {
    int gid  = blockIdx.x * blockDim.x + threadIdx.x;
    int row  = gid >> 5;
    int lane = gid & 31;
    if (row >= M) return;
    float4 v = ((const float4*)(h + (size_t)row * D))[lane];
    float r[4];
    #pragma unroll
    for (int o = 0; o < 4; ++o) {
        float4 wv = ((const float4*)(w + o * D))[lane];
        float p = v.x * wv.x + v.y * wv.y + v.z * wv.z + v.w * wv.w;
        #pragma unroll
        for (int s = 16; s > 0; s >>= 1)
            p += __shfl_xor_sync(0xffffffffu, p, s);
        r[o] = p;
    }
    if (lane == 0) {
        float4 o4 = make_float4(r[0] + b[0], r[1] + b[1], r[2] + b[2], r[3] + b[3]);
        *(float4*)(out + (size_t)row * 4) = o4;
    }
}

// ---------------------------------------------------------------------------
extern "C" void kernel_launch(void* const* d_in, const int* in_sizes, int n_in,
                              void* d_out, int out_size) {
    const float* x     = (const float*)d_in[0];
    const int*   ei    = (const int*)  d_in[1];
    const float* w1_l  = (const float*)d_in[2];
    const float* b1_l  = (const float*)d_in[3];
    const float* w1_r  = (const float*)d_in[4];
    const float* w2_l  = (const float*)d_in[5];
    const float* b2_l  = (const float*)d_in[6];
    const float* w2_r  = (const float*)d_in[7];
    const float* w_out = (const float*)d_in[8];
    const float* b_out = (const float*)d_in[9];
    float*       out   = (float*)d_out;

    const int E   = in_sizes[1] / 2;
    const int* src = ei;
    const int* dst = ei + E;

    float *agg, *h1, *h2, *deg;
    cudaGetSymbolAddress((void**)&agg, g_agg);
    cudaGetSymbolAddress((void**)&h1,  g_h1);
    cudaGetSymbolAddress((void**)&h2,  g_h2);
    cudaGetSymbolAddress((void**)&deg, g_deg);

    const int M        = N_NODES;
    const int agg4     = M * D / 4;                       // 3.2M float4
    const int deg4     = M / 4;
    const int zb_agg   = (agg4 + 255) / 256;
    const int zb_deg   = (deg4 + 255) / 256;
    const int sc_blk   = (E * 32 + 255) / 256;            // one warp per edge
    const int inv_blk  = (M + 255) / 256;
    const int gemm_blk = (M + 63) / 64;
    const int out_blk  = (M * 32 + 255) / 256;

    // ---- Layer 1 ----
    k_zero<<<zb_agg, 256>>>(agg, agg4);
    k_zero<<<zb_deg, 256>>>(deg, deg4);
    k_scatter<<<sc_blk, 256>>>(x, src, dst, agg, deg, E);
    k_invdeg<<<inv_blk, 256>>>(deg, M);
    k_sage_gemm<true><<<gemm_blk, 256>>>(agg, deg, x, w1_l, b1_l, w1_r, h1, M);

    // ---- Layer 2 (reuse inv degree) ----
    k_zero<<<zb_agg, 256>>>(agg, agg4);
    k_scatter<<<sc_blk, 256>>>(h1, src, dst, agg, nullptr, E);
    k_sage_gemm<true><<<gemm_blk, 256>>>(agg, deg, h1, w2_l, b2_l, w2_r, h2, M);

    // ---- Output projection ----
    k_out<<<out_blk, 256>>>(h2, w_out, b_out, out, M);
}

// round 5
// speedup vs baseline: 2.3170x; 2.3170x over previous
#include <cuda_runtime.h>
#include <cstdint>

#define N_NODES 100000
#define D 128

// ---------------- device scratch (no allocations allowed) -------------------
__device__ float g_agg[N_NODES * D];      // aggregated means
__device__ float g_h1 [N_NODES * D];      // layer-1 activations
__device__ float g_h2 [N_NODES * D];      // layer-2 activations
__device__ int   g_cnt[N_NODES];          // degree histogram
__device__ int   g_rowstart[N_NODES + 1]; // CSR offsets
__device__ int   g_cursor[N_NODES];       // permute cursors
__device__ int   g_bsums[512];            // scan block sums
__device__ int   g_perm[2000000];         // dst-sorted src indices

// ---------------------------------------------------------------------------
__global__ void k_zero_i4(int4* __restrict__ p, int n4) {
    int i = blockIdx.x * blockDim.x + threadIdx.x;
    if (i < n4) p[i] = make_int4(0, 0, 0, 0);
}

// ---------------------------------------------------------------------------
// degree histogram over dst
// ---------------------------------------------------------------------------
__global__ void k_hist(const int* __restrict__ dst, int* __restrict__ cnt, int E) {
    int e = blockIdx.x * blockDim.x + threadIdx.x;
    if (e < E) atomicAdd(cnt + __ldg(dst + e), 1);
}

// ---------------------------------------------------------------------------
// two-level exclusive scan: per-block scan, scan of block sums, apply
// ---------------------------------------------------------------------------
__global__ void k_scan1(const int* __restrict__ cnt, int* __restrict__ excl,
                        int* __restrict__ bsums, int n) {
    __shared__ int s[256];
    int t = threadIdx.x, i = blockIdx.x * 256 + t;
    int v = (i < n) ? cnt[i] : 0;
    s[t] = v; __syncthreads();
    #pragma unroll
    for (int off = 1; off < 256; off <<= 1) {
        int u = (t >= off) ? s[t - off] : 0;
        __syncthreads();
        s[t] += u;
        __syncthreads();
    }
    if (i < n) excl[i] = s[t] - v;              // exclusive
    if (t == 255) bsums[blockIdx.x] = s[255];
}

__global__ void k_scan2(int* __restrict__ bsums, int nb) {
    __shared__ int s[512];
    int t = threadIdx.x;
    int v = (t < nb) ? bsums[t] : 0;
    s[t] = v; __syncthreads();
    #pragma unroll
    for (int off = 1; off < 512; off <<= 1) {
        int u = (t >= off) ? s[t - off] : 0;
        __syncthreads();
        s[t] += u;
        __syncthreads();
    }
    if (t < nb) bsums[t] = s[t] - v;            // exclusive
}

__global__ void k_scan3(int* __restrict__ rowstart, const int* __restrict__ bsums,
                        int* __restrict__ cursor, int n, int E) {
    int i = blockIdx.x * blockDim.x + threadIdx.x;
    if (i < n) {
        int r = rowstart[i] + bsums[blockIdx.x * 256 / 256 + (i >> 8)];
        r = rowstart[i] + bsums[i >> 8];
        rowstart[i] = r;
        cursor[i]   = r;
    }
    if (i == 0) rowstart[n] = E;
}

// ---------------------------------------------------------------------------
// scatter edges into dst-sorted permutation
// ---------------------------------------------------------------------------
__global__ void k_permute(const int* __restrict__ src, const int* __restrict__ dst,
                          int* __restrict__ cursor, int* __restrict__ perm, int E) {
    int e = blockIdx.x * blockDim.x + threadIdx.x;
    if (e < E) {
        int pos = atomicAdd(cursor + __ldg(dst + e), 1);
        perm[pos] = __ldg(src + e);
    }
}

// ---------------------------------------------------------------------------
// CSR gather-mean: one warp per node, lane owns 4 feature columns.
// agg[n,:] = mean_{s in N(n)} x[s,:]     (no atomics, no zero-fill)
// ---------------------------------------------------------------------------
__global__ void __launch_bounds__(256)
k_gather(const float* __restrict__ x, const int* __restrict__ perm,
         const int* __restrict__ rowstart, float* __restrict__ agg) {
    int node = blockIdx.x * 8 + (threadIdx.x >> 5);
    int lane = threadIdx.x & 31;
    if (node >= N_NODES) return;
    int beg = __ldg(rowstart + node);
    int end = __ldg(rowstart + node + 1);
    float4 acc = make_float4(0.f, 0.f, 0.f, 0.f);
    int i = beg;
    int s = (i < end) ? __ldg(perm + i) : 0;
    while (i < end) {
        int s_next = (i + 1 < end) ? __ldg(perm + i + 1) : 0;  // prefetch
        float4 v = __ldg((const float4*)x + (size_t)s * 32 + lane);
        acc.x += v.x; acc.y += v.y; acc.z += v.z; acc.w += v.w;
        s = s_next; ++i;
    }
    float inv = 1.0f / (float)max(end - beg, 1);
    acc.x *= inv; acc.y *= inv; acc.z *= inv; acc.w *= inv;
    ((float4*)agg)[(size_t)node * 32 + lane] = acc;
}

// ---------------------------------------------------------------------------
// tf32 tensor-core SAGE GEMM:
//   out = act( agg @ Wl^T + bias + A2 @ Wr^T )
// Block tile 128x128, K = 2 x 128, 8 warps (4x2), warp tile 32x64, mma m16n8k8.
// ---------------------------------------------------------------------------
__device__ __forceinline__ float to_tf32(float x) {
    uint32_t u;
    asm("cvt.rna.tf32.f32 %0, %1;" : "=r"(u) : "f"(x));
    return __uint_as_float(u);
}

__device__ __forceinline__ void mma8(float* c, const uint32_t* a,
                                     uint32_t b0, uint32_t b1) {
    asm volatile(
        "mma.sync.aligned.m16n8k8.row.col.f32.tf32.tf32.f32 "
        "{%0,%1,%2,%3},{%4,%5,%6,%7},{%8,%9},{%0,%1,%2,%3};"
        : "+f"(c[0]), "+f"(c[1]), "+f"(c[2]), "+f"(c[3])
        : "r"(a[0]), "r"(a[1]), "r"(a[2]), "r"(a[3]), "r"(b0), "r"(b1));
}

#define AS_STRIDE 20     // conflict-free for frag-A LDS pattern
#define BS_STRIDE 136    // conflict-free for frag-B LDS pattern

template<bool RELU>
__global__ void __launch_bounds__(256)
k_sage_gemm(const float* __restrict__ A1,   // agg (already mean)
            const float* __restrict__ A2,   // x or h1
            const float* __restrict__ Wl,
            const float* __restrict__ bias,
            const float* __restrict__ Wr,
            float* __restrict__ out, int M) {
    __shared__ float As[128 * AS_STRIDE];
    __shared__ float Bs[16 * BS_STRIDE];

    const int t    = threadIdx.x;
    const int lane = t & 31;
    const int wid  = t >> 5;
    const int wm   = wid & 3;       // warp row-tile 0..3  (32 rows each)
    const int wn   = wid >> 2;      // warp col-tile 0..1  (64 cols each)
    const int m0   = blockIdx.x * 128;
    const int g    = lane >> 2;     // group 0..7
    const int q    = lane & 3;      // 0..3

    float c[2][8][4];
    #pragma unroll
    for (int mt = 0; mt < 2; ++mt)
        #pragma unroll
        for (int nt = 0; nt < 8; ++nt)
            #pragma unroll
            for (int j = 0; j < 4; ++j) c[mt][nt][j] = 0.f;

    #pragma unroll
    for (int p = 0; p < 2; ++p) {
        const float* A = p ? A2 : A1;
        const float* W = p ? Wr : Wl;
        for (int kc = 0; kc < D; kc += 16) {
            // ---- stage A: 128 rows x 16 k ----
            {
                int row = t >> 1;
                int kq  = (t & 1) * 8;
                int rg  = m0 + row;
                float4 v0 = make_float4(0.f,0.f,0.f,0.f);
                float4 v1 = make_float4(0.f,0.f,0.f,0.f);
                if (rg < M) {
                    const float4* ap = (const float4*)(A + (size_t)rg * D + kc + kq);
                    v0 = ap[0]; v1 = ap[1];
                }
                float* d = As + row * AS_STRIDE + kq;
                d[0] = to_tf32(v0.x); d[1] = to_tf32(v0.y);
                d[2] = to_tf32(v0.z); d[3] = to_tf32(v0.w);
                d[4] = to_tf32(v1.x); d[5] = to_tf32(v1.y);
                d[6] = to_tf32(v1.z); d[7] = to_tf32(v1.w);
            }
            // ---- stage B (transposed): Bs[k][n] = W[n][kc+k] ----
            {
                int n  = t >> 1;
                int kq = (t & 1) * 8;
                const float4* wp = (const float4*)(W + (size_t)n * D + kc + kq);
                float4 u0 = wp[0], u1 = wp[1];
                Bs[(kq+0)*BS_STRIDE + n] = to_tf32(u0.x);
                Bs[(kq+1)*BS_STRIDE + n] = to_tf32(u0.y);
                Bs[(kq+2)*BS_STRIDE + n] = to_tf32(u0.z);
                Bs[(kq+3)*BS_STRIDE + n] = to_tf32(u0.w);
                Bs[(kq+4)*BS_STRIDE + n] = to_tf32(u1.x);
                Bs[(kq+5)*BS_STRIDE + n] = to_tf32(u1.y);
                Bs[(kq+6)*BS_STRIDE + n] = to_tf32(u1.z);
                Bs[(kq+7)*BS_STRIDE + n] = to_tf32(u1.w);
            }
            __syncthreads();
            #pragma unroll
            for (int k0 = 0; k0 < 16; k0 += 8) {
                uint32_t a[2][4];
                #pragma unroll
                for (int mt = 0; mt < 2; ++mt) {
                    int rb = wm * 32 + mt * 16 + g;
                    a[mt][0] = __float_as_uint(As[(rb    ) * AS_STRIDE + k0 + q    ]);
                    a[mt][1] = __float_as_uint(As[(rb + 8) * AS_STRIDE + k0 + q    ]);
                    a[mt][2] = __float_as_uint(As[(rb    ) * AS_STRIDE + k0 + q + 4]);
                    a[mt][3] = __float_as_uint(As[(rb + 8) * AS_STRIDE + k0 + q + 4]);
                }
                #pragma unroll
                for (int nt = 0; nt < 8; ++nt) {
                    int col = wn * 64 + nt * 8 + g;
                    uint32_t b0 = __float_as_uint(Bs[(k0 + q    ) * BS_STRIDE + col]);
                    uint32_t b1 = __float_as_uint(Bs[(k0 + q + 4) * BS_STRIDE + col]);
                    mma8(c[0][nt], a[0], b0, b1);
                    mma8(c[1][nt], a[1], b0, b1);
                }
            }
            __syncthreads();
        }
    }

    // ---- epilogue: bias + relu + store ----
    #pragma unroll
    for (int mt = 0; mt < 2; ++mt) {
        #pragma unroll
        for (int nt = 0; nt < 8; ++nt) {
            int row = m0 + wm * 32 + mt * 16 + g;
            int col = wn * 64 + nt * 8 + q * 2;
            float b0 = __ldg(bias + col);
            float b1 = __ldg(bias + col + 1);
            float v0 = c[mt][nt][0] + b0, v1 = c[mt][nt][1] + b1;
            float v2 = c[mt][nt][2] + b0, v3 = c[mt][nt][3] + b1;
            if (RELU) {
                v0 = fmaxf(v0, 0.f); v1 = fmaxf(v1, 0.f);
                v2 = fmaxf(v2, 0.f); v3 = fmaxf(v3, 0.f);
            }
            if (row < M)
                *(float2*)(out + (size_t)row * D + col) = make_float2(v0, v1);
            if (row + 8 < M)
                *(float2*)(out + (size_t)(row + 8) * D + col) = make_float2(v2, v3);
        }
    }
}

// ---------------------------------------------------------------------------
// Output layer: out[m, 0..3] = h[m,:] @ w_out^T + b_out.  One warp per row.
// ---------------------------------------------------------------------------
__global__ void k_out(const float* __restrict__ h,
                      const float* __restrict__ w,
                      const float* __restrict__ b,
                      float* __restrict__ out, int M) {
    int gid  = blockIdx.x * blockDim.x + threadIdx.x;
    int row  = gid >> 5;
    int lane = gid & 31;
    if (row >= M) return;
    float4 v = ((const float4*)(h + (size_t)row * D))[lane];
    float r[4];
    #pragma unroll
    for (int o = 0; o < 4; ++o) {
        float4 wv = ((const float4*)(w + o * D))[lane];
        float p = v.x * wv.x + v.y * wv.y + v.z * wv.z + v.w * wv.w;
        #pragma unroll
        for (int s = 16; s > 0; s >>= 1)
            p += __shfl_xor_sync(0xffffffffu, p, s);
        r[o] = p;
    }
    if (lane == 0) {
        float4 o4 = make_float4(r[0] + b[0], r[1] + b[1], r[2] + b[2], r[3] + b[3]);
        *(float4*)(out + (size_t)row * 4) = o4;
    }
}

// ---------------------------------------------------------------------------
extern "C" void kernel_launch(void* const* d_in, const int* in_sizes, int n_in,
                              void* d_out, int out_size) {
    const float* x     = (const float*)d_in[0];
    const int*   ei    = (const int*)  d_in[1];
    const float* w1_l  = (const float*)d_in[2];
    const float* b1_l  = (const float*)d_in[3];
    const float* w1_r  = (const float*)d_in[4];
    const float* w2_l  = (const float*)d_in[5];
    const float* b2_l  = (const float*)d_in[6];
    const float* w2_r  = (const float*)d_in[7];
    const float* w_out = (const float*)d_in[8];
    const float* b_out = (const float*)d_in[9];
    float*       out   = (float*)d_out;

    const int E    = in_sizes[1] / 2;
    const int* src = ei;
    const int* dst = ei + E;

    float *agg, *h1, *h2;
    int *cnt, *rowstart, *cursor, *bsums, *perm;
    cudaGetSymbolAddress((void**)&agg,      g_agg);
    cudaGetSymbolAddress((void**)&h1,       g_h1);
    cudaGetSymbolAddress((void**)&h2,       g_h2);
    cudaGetSymbolAddress((void**)&cnt,      g_cnt);
    cudaGetSymbolAddress((void**)&rowstart, g_rowstart);
    cudaGetSymbolAddress((void**)&cursor,   g_cursor);
    cudaGetSymbolAddress((void**)&bsums,    g_bsums);
    cudaGetSymbolAddress((void**)&perm,     g_perm);

    const int M       = N_NODES;
    const int nb_scan = (M + 255) / 256;            // 391
    const int eb      = (E + 255) / 256;
    const int gath_b  = (M + 7) / 8;                // 8 warps / block
    const int gemm_b  = (M + 127) / 128;
    const int out_b   = (M * 32 + 255) / 256;

    // ---- CSR build (once, reused by both layers) ----
    k_zero_i4<<<(M/4 + 255) / 256, 256>>>((int4*)cnt, M / 4);
    k_hist   <<<eb, 256>>>(dst, cnt, E);
    k_scan1  <<<nb_scan, 256>>>(cnt, rowstart, bsums, M);
    k_scan2  <<<1, 512>>>(bsums, nb_scan);
    k_scan3  <<<nb_scan, 256>>>(rowstart, bsums, cursor, M, E);
    k_permute<<<eb, 256>>>(src, dst, cursor, perm, E);

    // ---- Layer 1 ----
    k_gather<<<gath_b, 256>>>(x, perm, rowstart, agg);
    k_sage_gemm<true><<<gemm_b, 256>>>(agg, x, w1_l, b1_l, w1_r, h1, M);

    // ---- Layer 2 ----
    k_gather<<<gath_b, 256>>>(h1, perm, rowstart, agg);
    k_sage_gemm<true><<<gemm_b, 256>>>(agg, h1, w2_l, b2_l, w2_r, h2, M);

    // ---- Output projection ----
    k_out<<<out_b, 256>>>(h2, w_out, b_out, out, M);
}